// round 16
// baseline (speedup 1.0000x reference)
#include <cuda_runtime.h>
#include <stdint.h>
#include <math.h>

#define NCH   31
#define NREG  9
#define RPB   16
#define TPB   512
#define NBAND 2418            // 78 band groups * 31 channels (tiles 0..2417)
#define NSTRM 1550            // 50 stream groups * 31 channels
#define NTILES (NBAND + NSTRM)
#define PGRID 296             // persistent blocks (2 per SM)
#define DEPTH 4               // pipeline stages
#define CROWS 2               // rows per chunk
#define CPT   (RPB / CROWS)   // 8 chunks per tile
#define STAGE_BYTES (CROWS * 2048 * 4)       // 16384
#define SEG_BYTES   1600                      // 400 floats per segment
#define PSTAGE_BYTES (CROWS * 3 * SEG_BYTES)  // 9600
#define DYN_BYTES (DEPTH * STAGE_BYTES + DEPTH * PSTAGE_BYTES)   // 103936
#define SCRATCH_N (1 + NREG * NCH * 7)

// scratch[0] = global target sum; per (r,c): {St1, St3, Sxt3, Syt3, Sp3, Sxp3, Syp3}
__device__ double g_scratch[SCRATCH_N];
__device__ unsigned int g_cnt  = 0;
__device__ unsigned int g_tile = 0;

__device__ __forceinline__ float wsumf(float v) {
#pragma unroll
    for (int o = 16; o; o >>= 1) v += __shfl_down_sync(0xffffffffu, v, o);
    return v;
}
__device__ __forceinline__ double wsumd(double v) {
#pragma unroll
    for (int o = 16; o; o >>= 1) v += __shfl_down_sync(0xffffffffu, v, o);
    return v;
}
__device__ __forceinline__ uint32_t s2u(const void* p) {
    uint32_t a;
    asm("{ .reg .u64 t; cvta.to.shared.u64 t, %1; cvt.u32.u64 %0, t; }"
        : "=r"(a) : "l"(p));
    return a;
}
__device__ __forceinline__ void decode_tile(int t, int& ch, int& y0, int& rbm, int& bs) {
    if (t < NBAND) {
        ch = t / 78; const int i = t % 78; int g;
        if      (i < 26) { rbm = 0; g = 12 + i; bs = 200;  }
        else if (i < 52) { rbm = 1; g = 36 + i; bs = 1000; }
        else             { rbm = 2; g = 41 + i; bs = 1500; }
        y0 = g * RPB;
    } else {
        const int s2 = t - NBAND;
        ch = s2 / 50; const int i = s2 % 50; rbm = -1; bs = 0;
        const int g = (i < 12) ? i : (i < 36) ? 26 + i : (i < 41) ? 52 + i : 78 + i;
        y0 = g * RPB;
    }
}
__device__ __forceinline__ void mbar_wait(uint32_t mb, int par) {
    asm volatile(
        "{\n\t.reg .pred P;\n"
        "LW_%=:\n\tmbarrier.try_wait.parity.acquire.cta.shared::cta.b64 P, [%0], %1, 0x989680;\n"
        "\t@P bra LD_%=;\n\tbra LW_%=;\n"
        "LD_%=:\n\t}"
        :: "r"(mb), "r"(par) : "memory");
}
__device__ __forceinline__ void mbar_arrive(uint32_t mb) {
    asm volatile("mbarrier.arrive.shared.b64 _, [%0];" :: "r"(mb) : "memory");
}

// issue chunk gi of tile `t`: CROWS targ rows (+ pred segments for in-band rows).
__device__ __forceinline__ void issue_chunk_dyn(
    int gi, int t, const float* __restrict__ targ, const float* __restrict__ pred,
    uint32_t mbar0, uint32_t tstage0, uint32_t pstage0) {
    int ch, y0, rbm, bs;
    decode_tile(t, ch, y0, rbm, bs);
    const int row0 = y0 + (gi % CPT) * CROWS;
    const bool band = (rbm >= 0) && ((unsigned)(row0 - bs) < 400u);
    const size_t base = ((size_t)ch << 22) + ((size_t)row0 << 11);
    const int st = gi % DEPTH;
    const uint32_t mb = mbar0 + 8 * st;
    asm volatile("mbarrier.arrive.expect_tx.shared.b64 _, [%0], %1;"
                 :: "r"(mb), "r"(band ? STAGE_BYTES + PSTAGE_BYTES : STAGE_BYTES)
                 : "memory");
    asm volatile("cp.async.bulk.shared::cta.global.mbarrier::complete_tx::bytes "
                 "[%0], [%1], %2, [%3];"
                 :: "r"(tstage0 + st * STAGE_BYTES), "l"((const void*)(targ + base)),
                    "r"(STAGE_BYTES), "r"(mb) : "memory");
    if (band) {
        const uint32_t dst = pstage0 + st * PSTAGE_BYTES;
#pragma unroll
        for (int r = 0; r < CROWS; r++) {
#pragma unroll
            for (int s = 0; s < 3; s++) {
                const int xoff = (s == 0) ? 200 : (s == 1) ? 1000 : 1500;
                asm volatile("cp.async.bulk.shared::cta.global.mbarrier::complete_tx::bytes "
                             "[%0], [%1], %2, [%3];"
                             :: "r"(dst + (r * 3 + s) * SEG_BYTES),
                                "l"((const void*)(pred + base + ((size_t)r << 11) + xoff)),
                                "r"(SEG_BYTES), "r"(mb) : "memory");
            }
        }
    }
}

__global__ __launch_bounds__(TPB, 2) void coml_kernel(
    const float* __restrict__ pred, const float* __restrict__ targ,
    float* __restrict__ out) {
    extern __shared__ char dyn[];
    __shared__ alignas(8) unsigned long long sh_mbar[DEPTH];
    __shared__ int sh_tiles[4];          // tile-id ring, indexed by (chunk/CPT)&3
    __shared__ alignas(16) float sh_red[7 * 304];
    __shared__ double wpart[16];
    __shared__ unsigned int ticket;

    const int tid = threadIdx.x, lane = tid & 31, wid = tid >> 5;

    // thread col-band (float4 index == tid; all edges multiples of 4)
    int cb = -1, bxs = 0;
    if      (tid >= 50  && tid < 150) { cb = 0; bxs = 50;  }
    else if (tid >= 250 && tid < 350) { cb = 1; bxs = 250; }
    else if (tid >= 375 && tid < 475) { cb = 2; bxs = 375; }
    const float offb = (float)((tid - bxs) * 4);
    const int cidx = (cb >= 0) ? cb * 100 + (tid - bxs) : -1;

    const uint32_t mbar0   = s2u(&sh_mbar[0]);
    const uint32_t tstage0 = s2u(dyn);
    const uint32_t pstage0 = tstage0 + DEPTH * STAGE_BYTES;
    const char* pstage_c   = dyn + DEPTH * STAGE_BYTES;

    if (tid == 0) {
        for (int s = 0; s < DEPTH; s++)
            asm volatile("mbarrier.init.shared.b64 [%0], %1;"
                         :: "r"(mbar0 + 8 * s), "r"(1) : "memory");
    }
    __syncthreads();

    bool done_issue = false;
    if (tid == 0) {
        // prime: fetch tile slot 0 and issue the first DEPTH chunks (all slot 0, DEPTH<CPT)
        const int t0 = (int)atomicAdd(&g_tile, 1u);
        sh_tiles[0] = t0;                 // t0 < NTILES (NTILES >> PGRID)
#pragma unroll
        for (int gi = 0; gi < DEPTH; gi++)
            issue_chunk_dyn(gi, t0, targ, pred, mbar0, tstage0, pstage0);
    }

    float gsum = 0.f;
    float SA[7] = {0.f, 0.f, 0.f, 0.f, 0.f, 0.f, 0.f};

    for (int g = 0;; g++) {
        const int st = g % DEPTH, par = (g / DEPTH) & 1;
        mbar_wait(mbar0 + 8 * st, par);
        const int t = sh_tiles[(g / CPT) & 3];   // acquire-ordered after the wait
        if (t >= NTILES) break;                  // sentinel: no more tiles
        int ch, y0, rbm, bs;
        decode_tile(t, ch, y0, rbm, bs);

        const float4* sp = (const float4*)(dyn + st * STAGE_BYTES) + tid;
        const int row0 = y0 + (g % CPT) * CROWS;
        if (rbm < 0 || (unsigned)(row0 - bs) >= 400u) {
            const float4 a = sp[0];
            const float4 b = sp[512];
            gsum += ((a.x + a.y) + (a.z + a.w)) + ((b.x + b.y) + (b.z + b.w));
        } else {
            const char* pk = pstage_c + st * PSTAGE_BYTES;
#pragma unroll
            for (int r = 0; r < CROWS; r++) {
                const float4 v = sp[r * 512];
                const float s1 = (v.x + v.y) + (v.z + v.w);
                gsum += s1;
                if (cb >= 0) {
                    const float i0f = (float)(row0 + r - bs);
                    SA[0] += s1;
                    const float a3 = v.x*v.x*v.x, b3 = v.y*v.y*v.y;
                    const float c3 = v.z*v.z*v.z, d3 = v.w*v.w*v.w;
                    const float s3 = (a3 + b3) + (c3 + d3);
                    SA[1] += s3;
                    SA[2] = fmaf(i0f, s3, SA[2]);
                    SA[3] += fmaf(offb, s3, b3 + 2.f*c3 + 3.f*d3);
                    const float4 p = *(const float4*)(pk + (r * 3 + cb) * SEG_BYTES
                                                       + (size_t)(tid - bxs) * 16);
                    const float e3 = p.x*p.x*p.x, f3 = p.y*p.y*p.y;
                    const float g3 = p.z*p.z*p.z, h3 = p.w*p.w*p.w;
                    const float sp3 = (e3 + f3) + (g3 + h3);
                    SA[4] += sp3;
                    SA[5] = fmaf(i0f, sp3, SA[5]);
                    SA[6] += fmaf(offb, sp3, f3 + 2.f*g3 + 3.f*h3);
                }
            }
        }
        __syncthreads();   // stage consumed -> safe to refill
        if (tid == 0 && !done_issue) {
            const int gi = g + DEPTH;
            if ((gi % CPT) == 0) {
                const int tt = (int)atomicAdd(&g_tile, 1u);
                sh_tiles[(gi / CPT) & 3] = tt;
                if (tt >= NTILES) {
                    mbar_arrive(mbar0 + 8 * (gi % DEPTH));   // sentinel phase flip
                    done_issue = true;
                } else {
                    issue_chunk_dyn(gi, tt, targ, pred, mbar0, tstage0, pstage0);
                }
            } else {
                const int tt = sh_tiles[(gi / CPT) & 3];     // same slot, already fetched
                issue_chunk_dyn(gi, tt, targ, pred, mbar0, tstage0, pstage0);
            }
        }

        // band tile epilogue at the tile's final chunk
        if (rbm >= 0 && (g % CPT) == CPT - 1) {
            if (cidx >= 0) {
#pragma unroll
                for (int k = 0; k < 7; k++) { sh_red[k * 304 + cidx] = SA[k]; SA[k] = 0.f; }
            }
            __syncthreads();
            for (int item = wid; item < 21; item += 16) {
                const int b = item / 7, stt = item % 7, lo = b * 100;
                float s = 0.f;
                for (int i2 = lo + lane; i2 < lo + 100; i2 += 32)
                    s += sh_red[stt * 304 + i2];
                s = wsumf(s);
                if (lane == 0) {
                    const int r = rbm * 3 + b;
                    atomicAdd(&g_scratch[1 + (r * NCH + ch) * 7 + stt], (double)s);
                }
            }
        }
    }

    // ---- one gsum flush per CTA ----
    {
        const float v = wsumf(gsum);
        __syncthreads();
        if (lane == 0) sh_red[wid] = v;
        __syncthreads();
        if (tid == 0) {
            float s = 0.f;
#pragma unroll
            for (int w = 0; w < 16; w++) s += sh_red[w];
            atomicAdd(&g_scratch[0], (double)s);
        }
    }

    // ---- last CTA computes the loss and resets state ----
    __threadfence();
    if (tid == 0) ticket = atomicAdd(&g_cnt, 1u);
    __syncthreads();
    if (ticket == PGRID - 1) {
        __threadfence();
        volatile double* vs = g_scratch;
        const double mean_t = vs[0] / ((double)NCH * 2048.0 * 2048.0);
        double term = 0.0;
        if (tid < NREG * NCH) {
            const int r = tid / NCH;
            const double St1  = vs[1 + tid*7 + 0], St3  = vs[1 + tid*7 + 1];
            const double Sxt3 = vs[1 + tid*7 + 2], Syt3 = vs[1 + tid*7 + 3];
            const double Sp3  = vs[1 + tid*7 + 4], Sxp3 = vs[1 + tid*7 + 5];
            const double Syp3 = vs[1 + tid*7 + 6];
            const double cxt = (St3 != 0.0) ? Sxt3 / St3 : 0.0;
            const double cyt = (St3 != 0.0) ? Syt3 / St3 : 0.0;
            const double cxp = (Sp3 != 0.0) ? Sxp3 / Sp3 : 0.0;
            const double cyp = (Sp3 != 0.0) ? Syp3 / Sp3 : 0.0;
            const double dx = cxp - cxt, dy = cyp - cyt;
            term = sqrt(dx * dx + dy * dy) * ((St1 / 160000.0) / mean_t);
            if (r == 4) term *= 5.0;  // fundamental region weight
        }
        term = wsumd(term);
        if (lane == 0) wpart[wid] = term;
        __syncthreads();
        if (tid == 0) {
            double s = 0.0;
#pragma unroll
            for (int w = 0; w < 16; w++) s += wpart[w];
            out[0] = (float)(s / (double)(NREG * NCH));
            g_cnt  = 0;
            g_tile = 0;
        }
        for (int i = tid; i < SCRATCH_N; i += TPB) g_scratch[i] = 0.0;
    }
}

extern "C" void kernel_launch(void* const* d_in, const int* in_sizes, int n_in,
                              void* d_out, int out_size) {
    const float* pred = (const float*)d_in[0];
    const float* targ = (const float*)d_in[1];
    static int attr_done = 0;
    if (!attr_done) {
        cudaFuncSetAttribute(coml_kernel, cudaFuncAttributeMaxDynamicSharedMemorySize, DYN_BYTES);
        attr_done = 1;
    }
    coml_kernel<<<PGRID, TPB, DYN_BYTES>>>(pred, targ, (float*)d_out);
}

// round 17
// speedup vs baseline: 1.0342x; 1.0342x over previous
#include <cuda_runtime.h>
#include <stdint.h>
#include <math.h>

#define NCH   31
#define NREG  9
#define RPB   16
#define TPB   512
#define NBAND 2418            // 78 band groups * 31 channels
#define NSTRM 1550            // 50 stream groups * 31 channels
#define NTILES (NBAND + NSTRM)
#define PGRID 296             // persistent blocks (2 per SM)
#define DEPTH 2               // pipeline stages
#define CROWS 4               // rows per chunk (band edges are 4-row aligned in-tile)
#define CPT   (RPB / CROWS)   // 4 chunks per tile
#define STAGE_BYTES (CROWS * 2048 * 4)       // 32768
#define SEG_BYTES   1600                      // 400 floats per segment
#define PSTAGE_BYTES (CROWS * 3 * SEG_BYTES)  // 19200
#define DYN_BYTES (DEPTH * STAGE_BYTES + DEPTH * PSTAGE_BYTES)   // 103936
#define SCRATCH_N (1 + NREG * NCH * 7)

// scratch[0] = global target sum; per (r,c): {St1, St3, Sxt3, Syt3, Sp3, Sxp3, Syp3}
__device__ double g_scratch[SCRATCH_N];
__device__ unsigned int g_cnt = 0;

__device__ __forceinline__ float wsumf(float v) {
#pragma unroll
    for (int o = 16; o; o >>= 1) v += __shfl_down_sync(0xffffffffu, v, o);
    return v;
}
__device__ __forceinline__ double wsumd(double v) {
#pragma unroll
    for (int o = 16; o; o >>= 1) v += __shfl_down_sync(0xffffffffu, v, o);
    return v;
}
__device__ __forceinline__ uint32_t s2u(const void* p) {
    uint32_t a;
    asm("{ .reg .u64 t; cvta.to.shared.u64 t, %1; cvt.u32.u64 %0, t; }"
        : "=r"(a) : "l"(p));
    return a;
}
__device__ __forceinline__ void decode_tile(int t, int& ch, int& y0, int& rbm, int& bs) {
    if (t < NBAND) {
        ch = t / 78; const int i = t % 78; int g;
        if      (i < 26) { rbm = 0; g = 12 + i; bs = 200;  }
        else if (i < 52) { rbm = 1; g = 36 + i; bs = 1000; }
        else             { rbm = 2; g = 41 + i; bs = 1500; }
        y0 = g * RPB;
    } else {
        const int s2 = t - NBAND;
        ch = s2 / 50; const int i = s2 % 50; rbm = -1; bs = 0;
        const int g = (i < 12) ? i : (i < 36) ? 26 + i : (i < 41) ? 52 + i : 78 + i;
        y0 = g * RPB;
    }
}
__device__ __forceinline__ void mbar_wait(uint32_t mb, int par) {
    asm volatile(
        "{\n\t.reg .pred P;\n"
        "LW_%=:\n\tmbarrier.try_wait.parity.acquire.cta.shared::cta.b64 P, [%0], %1, 0x989680;\n"
        "\t@P bra LD_%=;\n\tbra LW_%=;\n"
        "LD_%=:\n\t}"
        :: "r"(mb), "r"(par) : "memory");
}

// issue chunk g: CROWS targ rows (+ pred segments when the 4-row chunk is in a band;
// band edges are 4-row aligned within tiles, so the chunk is uniformly in or out).
__device__ __forceinline__ void issue_chunk(
    int g, int bid, const float* __restrict__ targ, const float* __restrict__ pred,
    uint32_t mbar0, uint32_t tstage0, uint32_t pstage0) {
    const int t = bid + (g / CPT) * PGRID;
    int ch, y0, rbm, bs;
    decode_tile(t, ch, y0, rbm, bs);
    const int row0 = y0 + (g % CPT) * CROWS;
    const bool band = (rbm >= 0) && ((unsigned)(row0 - bs) < 400u);
    const size_t base = ((size_t)ch << 22) + ((size_t)row0 << 11);
    const int st = g % DEPTH;
    const uint32_t mb = mbar0 + 8 * st;
    asm volatile("mbarrier.arrive.expect_tx.shared.b64 _, [%0], %1;"
                 :: "r"(mb), "r"(band ? STAGE_BYTES + PSTAGE_BYTES : STAGE_BYTES)
                 : "memory");
    asm volatile("cp.async.bulk.shared::cta.global.mbarrier::complete_tx::bytes "
                 "[%0], [%1], %2, [%3];"
                 :: "r"(tstage0 + st * STAGE_BYTES), "l"((const void*)(targ + base)),
                    "r"(STAGE_BYTES), "r"(mb) : "memory");
    if (band) {
        const uint32_t dst = pstage0 + st * PSTAGE_BYTES;
#pragma unroll
        for (int r = 0; r < CROWS; r++) {
#pragma unroll
            for (int s = 0; s < 3; s++) {
                const int xoff = (s == 0) ? 200 : (s == 1) ? 1000 : 1500;
                asm volatile("cp.async.bulk.shared::cta.global.mbarrier::complete_tx::bytes "
                             "[%0], [%1], %2, [%3];"
                             :: "r"(dst + (r * 3 + s) * SEG_BYTES),
                                "l"((const void*)(pred + base + ((size_t)r << 11) + xoff)),
                                "r"(SEG_BYTES), "r"(mb) : "memory");
            }
        }
    }
}

__global__ __launch_bounds__(TPB, 2) void coml_kernel(
    const float* __restrict__ pred, const float* __restrict__ targ,
    float* __restrict__ out) {
    extern __shared__ char dyn[];
    __shared__ alignas(8) unsigned long long sh_mbar[DEPTH];
    __shared__ alignas(16) float sh_red[7 * 304];
    __shared__ double wpart[16];
    __shared__ unsigned int ticket;

    const int tid = threadIdx.x, lane = tid & 31, wid = tid >> 5;
    const int bid = blockIdx.x;

    // thread col-band (float4 index == tid; all edges multiples of 4)
    int cb = -1, bxs = 0;
    if      (tid >= 50  && tid < 150) { cb = 0; bxs = 50;  }
    else if (tid >= 250 && tid < 350) { cb = 1; bxs = 250; }
    else if (tid >= 375 && tid < 475) { cb = 2; bxs = 375; }
    const float offb = (float)((tid - bxs) * 4);
    const int cidx = (cb >= 0) ? cb * 100 + (tid - bxs) : -1;

    const int ntile_cta = (NTILES - 1 - bid) / PGRID + 1;
    const int nch = ntile_cta * CPT;

    const uint32_t mbar0   = s2u(&sh_mbar[0]);
    const uint32_t tstage0 = s2u(dyn);
    const uint32_t pstage0 = tstage0 + DEPTH * STAGE_BYTES;
    const char* pstage_c   = dyn + DEPTH * STAGE_BYTES;

    if (tid == 0) {
        for (int s = 0; s < DEPTH; s++)
            asm volatile("mbarrier.init.shared.b64 [%0], %1;"
                         :: "r"(mbar0 + 8 * s), "r"(1) : "memory");
    }
    __syncthreads();
    if (tid == 0) {
        const int ni = nch < DEPTH ? nch : DEPTH;
        for (int g = 0; g < ni; g++)
            issue_chunk(g, bid, targ, pred, mbar0, tstage0, pstage0);
    }

    float gs0 = 0.f, gs1 = 0.f;
    float SA[7] = {0.f, 0.f, 0.f, 0.f, 0.f, 0.f, 0.f};

    for (int g = 0; g < nch; g++) {
        const int t = bid + (g / CPT) * PGRID;
        int ch, y0, rbm, bs;
        decode_tile(t, ch, y0, rbm, bs);
        const int st = g % DEPTH, par = (g / DEPTH) & 1;
        mbar_wait(mbar0 + 8 * st, par);

        const float4* sp = (const float4*)(dyn + st * STAGE_BYTES) + tid;
        const int row0 = y0 + (g % CPT) * CROWS;
        if (rbm < 0 || (unsigned)(row0 - bs) >= 400u) {
            const float4 a = sp[0];
            const float4 b = sp[512];
            const float4 c = sp[1024];
            const float4 d = sp[1536];
            gs0 += ((a.x + a.y) + (a.z + a.w)) + ((c.x + c.y) + (c.z + c.w));
            gs1 += ((b.x + b.y) + (b.z + b.w)) + ((d.x + d.y) + (d.z + d.w));
        } else {
            const char* pk = pstage_c + st * PSTAGE_BYTES;
#pragma unroll
            for (int r = 0; r < CROWS; r++) {
                const float4 v = sp[r * 512];
                const float s1 = (v.x + v.y) + (v.z + v.w);
                gs0 += s1;
                if (cb >= 0) {
                    const float i0f = (float)(row0 + r - bs);
                    SA[0] += s1;
                    const float a3 = v.x*v.x*v.x, b3 = v.y*v.y*v.y;
                    const float c3 = v.z*v.z*v.z, d3 = v.w*v.w*v.w;
                    const float s3 = (a3 + b3) + (c3 + d3);
                    SA[1] += s3;
                    SA[2] = fmaf(i0f, s3, SA[2]);
                    SA[3] += fmaf(offb, s3, b3 + 2.f*c3 + 3.f*d3);
                    const float4 p = *(const float4*)(pk + (r * 3 + cb) * SEG_BYTES
                                                       + (size_t)(tid - bxs) * 16);
                    const float e3 = p.x*p.x*p.x, f3 = p.y*p.y*p.y;
                    const float g3 = p.z*p.z*p.z, h3 = p.w*p.w*p.w;
                    const float sp3 = (e3 + f3) + (g3 + h3);
                    SA[4] += sp3;
                    SA[5] = fmaf(i0f, sp3, SA[5]);
                    SA[6] += fmaf(offb, sp3, f3 + 2.f*g3 + 3.f*h3);
                }
            }
        }
        __syncthreads();   // stage consumed -> safe to refill
        if (tid == 0 && g + DEPTH < nch)
            issue_chunk(g + DEPTH, bid, targ, pred, mbar0, tstage0, pstage0);

        // band tile epilogue at the tile's final chunk
        if (rbm >= 0 && (g % CPT) == CPT - 1) {
            if (cidx >= 0) {
#pragma unroll
                for (int k = 0; k < 7; k++) { sh_red[k * 304 + cidx] = SA[k]; SA[k] = 0.f; }
            }
            __syncthreads();
            for (int item = wid; item < 21; item += 16) {
                const int b = item / 7, stt = item % 7, lo = b * 100;
                float s = 0.f;
                for (int i2 = lo + lane; i2 < lo + 100; i2 += 32)
                    s += sh_red[stt * 304 + i2];
                s = wsumf(s);
                if (lane == 0) {
                    const int r = rbm * 3 + b;
                    atomicAdd(&g_scratch[1 + (r * NCH + ch) * 7 + stt], (double)s);
                }
            }
        }
    }

    // ---- one gsum flush per CTA ----
    {
        const float v = wsumf(gs0 + gs1);
        __syncthreads();
        if (lane == 0) sh_red[wid] = v;
        __syncthreads();
        if (tid == 0) {
            float s = 0.f;
#pragma unroll
            for (int w = 0; w < 16; w++) s += sh_red[w];
            atomicAdd(&g_scratch[0], (double)s);
        }
    }

    // ---- last CTA computes the loss and resets state ----
    __threadfence();
    if (tid == 0) ticket = atomicAdd(&g_cnt, 1u);
    __syncthreads();
    if (ticket == PGRID - 1) {
        __threadfence();
        volatile double* vs = g_scratch;
        const double mean_t = vs[0] / ((double)NCH * 2048.0 * 2048.0);
        double term = 0.0;
        if (tid < NREG * NCH) {
            const int r = tid / NCH;
            const double St1  = vs[1 + tid*7 + 0], St3  = vs[1 + tid*7 + 1];
            const double Sxt3 = vs[1 + tid*7 + 2], Syt3 = vs[1 + tid*7 + 3];
            const double Sp3  = vs[1 + tid*7 + 4], Sxp3 = vs[1 + tid*7 + 5];
            const double Syp3 = vs[1 + tid*7 + 6];
            const double cxt = (St3 != 0.0) ? Sxt3 / St3 : 0.0;
            const double cyt = (St3 != 0.0) ? Syt3 / St3 : 0.0;
            const double cxp = (Sp3 != 0.0) ? Sxp3 / Sp3 : 0.0;
            const double cyp = (Sp3 != 0.0) ? Syp3 / Sp3 : 0.0;
            const double dx = cxp - cxt, dy = cyp - cyt;
            term = sqrt(dx * dx + dy * dy) * ((St1 / 160000.0) / mean_t);
            if (r == 4) term *= 5.0;  // fundamental region weight
        }
        term = wsumd(term);
        if (lane == 0) wpart[wid] = term;
        __syncthreads();
        if (tid == 0) {
            double s = 0.0;
#pragma unroll
            for (int w = 0; w < 16; w++) s += wpart[w];
            out[0] = (float)(s / (double)(NREG * NCH));
            g_cnt = 0;
        }
        for (int i = tid; i < SCRATCH_N; i += TPB) g_scratch[i] = 0.0;
    }
}

extern "C" void kernel_launch(void* const* d_in, const int* in_sizes, int n_in,
                              void* d_out, int out_size) {
    const float* pred = (const float*)d_in[0];
    const float* targ = (const float*)d_in[1];
    static int attr_done = 0;
    if (!attr_done) {
        cudaFuncSetAttribute(coml_kernel, cudaFuncAttributeMaxDynamicSharedMemorySize, DYN_BYTES);
        attr_done = 1;
    }
    coml_kernel<<<PGRID, TPB, DYN_BYTES>>>(pred, targ, (float*)d_out);
}